// round 13
// baseline (speedup 1.0000x reference)
#include <cuda_runtime.h>
#include <cuda_fp16.h>
#include <math.h>
#include <stdint.h>

// ---------------- problem constants ----------------
#define T_TOK 4096
#define H_DIM 1024
#define F_DIM 2816
#define E_NUM 8
#define NROWS (T_TOK*2)
#define BM 128
#define RCAP (NROWS + E_NUM*BM)   // 9216
#define N1 (2*F_DIM)              // 5632
#define NBLK_ROUTER 32
// fused stage: A-hi | A-lo | B, each 128 rows x 80B
#define SUB1 10240
#define STAGE (3*SUB1)            // 30720
#define NSTG 3
#define SMEM_DYN (NSTG*STAGE)     // 92160
#define NK1 32                    // 1024/32
#define NK2 88                    // 2816/32
// prep kernel block partition
#define NB_T1 22528
#define NB_T2 22528
#define NB_CX 4096
#define NB_IN 36

// ---------------- device scratch ----------------
__device__ int   g_eidx[NROWS];
__device__ float g_wgt[NROWS];
__device__ int   g_cnt[E_NUM];
__device__ int   g_pos[NROWS];
__device__ int   g_list[RCAP];
__device__ float g_partsP[NBLK_ROUTER][E_NUM];

__device__ __align__(16) __half g_xhi[(size_t)T_TOK*H_DIM];
__device__ __align__(16) __half g_xlo[(size_t)T_TOK*H_DIM];
__device__ __align__(16) __half g_b1h[(size_t)E_NUM*N1*H_DIM];   // [e][n(gate|up)][h]
__device__ __align__(16) __half g_b2h[(size_t)E_NUM*H_DIM*F_DIM];// [e][n(h)][f]
__device__ __align__(16) __half g_hh[(size_t)RCAP*F_DIM];
__device__ __align__(16) __half g_hl[(size_t)RCAP*F_DIM];
__device__ __align__(16) float g_y[(size_t)NROWS*H_DIM];

// ---------------- PTX helpers ----------------
__device__ __forceinline__ uint32_t s2u(const void* p){
    uint32_t a;
    asm("{ .reg .u64 t; cvta.to.shared.u64 t, %1; cvt.u32.u64 %0, t; }" : "=r"(a) : "l"(p));
    return a;
}
__device__ __forceinline__ void cp16(uint32_t dst, const void* src, int n){
    asm volatile("cp.async.cg.shared.global [%0], [%1], 16, %2;" :: "r"(dst), "l"(src), "r"(n) : "memory");
}
__device__ __forceinline__ void cp_commit(){ asm volatile("cp.async.commit_group;" ::: "memory"); }
__device__ __forceinline__ void ldmx4(uint32_t* r, uint32_t addr){
    asm volatile("ldmatrix.sync.aligned.m8n8.x4.shared.b16 {%0,%1,%2,%3}, [%4];"
        : "=r"(r[0]),"=r"(r[1]),"=r"(r[2]),"=r"(r[3]) : "r"(addr));
}
__device__ __forceinline__ void mma16816(float* c, const uint32_t* a, uint32_t b0, uint32_t b1){
    asm volatile("mma.sync.aligned.m16n8k16.row.col.f32.f16.f16.f32 "
                 "{%0,%1,%2,%3},{%4,%5,%6,%7},{%8,%9},{%0,%1,%2,%3};"
        : "+f"(c[0]),"+f"(c[1]),"+f"(c[2]),"+f"(c[3])
        : "r"(a[0]),"r"(a[1]),"r"(a[2]),"r"(a[3]), "r"(b0),"r"(b1));
}
__device__ __forceinline__ void split2h(float v, __half& h, __half& l){
    h = __float2half_rn(v);
    l = __float2half_rn(v - __half2float(h));
}

// ---------------- prep: t1 + t2 + convx + init fused ----------------
__global__ void prep_kernel(const float* __restrict__ x,
                            const float* __restrict__ wg,
                            const float* __restrict__ wu,
                            const float* __restrict__ wd){
    __shared__ float sg[32][33], su[32][33];
    int b = blockIdx.x;
    int tid = threadIdx.x;
    int tx = tid & 31, ty = tid >> 5;

    if (b < NB_T1){
        int e = b / 2816, rem = b % 2816;
        int h0 = (rem / 88) * 32, f0 = (rem % 88) * 32;
        const float* pg = wg + ((size_t)e*H_DIM + h0)*F_DIM + f0;
        const float* pu = wu + ((size_t)e*H_DIM + h0)*F_DIM + f0;
#pragma unroll
        for (int j = 0; j < 4; j++){
            int hl = ty + j*8;
            sg[hl][tx] = pg[(size_t)hl*F_DIM + tx];
            su[hl][tx] = pu[(size_t)hl*F_DIM + tx];
        }
        __syncthreads();
#pragma unroll
        for (int j = 0; j < 4; j++){
            int fl = ty + j*8;
            size_t ng = ((size_t)e*N1 + f0 + fl)*H_DIM + h0 + tx;
            size_t nu = ((size_t)e*N1 + F_DIM + f0 + fl)*H_DIM + h0 + tx;
            g_b1h[ng] = __float2half_rn(sg[tx][fl]);
            g_b1h[nu] = __float2half_rn(su[tx][fl]);
        }
    } else if (b < NB_T1 + NB_T2){
        int bb = b - NB_T1;
        int e = bb / 2816, rem = bb % 2816;
        int h0 = (rem / 88) * 32, f0 = (rem % 88) * 32;
        const float* pd = wd + ((size_t)e*F_DIM + f0)*H_DIM + h0;
#pragma unroll
        for (int j = 0; j < 4; j++){
            int fl = ty + j*8;
            sg[fl][tx] = pd[(size_t)fl*H_DIM + tx];
        }
        __syncthreads();
#pragma unroll
        for (int j = 0; j < 4; j++){
            int hl = ty + j*8;
            size_t o = ((size_t)e*H_DIM + h0 + hl)*F_DIM + f0 + tx;
            g_b2h[o] = __float2half_rn(sg[tx][hl]);
        }
    } else if (b < NB_T1 + NB_T2 + NB_CX){
        int i = (b - NB_T1 - NB_T2)*256 + tid;
        float4 v = ((const float4*)x)[i];
        __half h0,l0,h1,l1,h2,l2,h3,l3;
        split2h(v.x,h0,l0); split2h(v.y,h1,l1); split2h(v.z,h2,l2); split2h(v.w,h3,l3);
        uint32_t hA = (uint32_t)__half_as_ushort(h0) | ((uint32_t)__half_as_ushort(h1)<<16);
        uint32_t hB = (uint32_t)__half_as_ushort(h2) | ((uint32_t)__half_as_ushort(h3)<<16);
        uint32_t lA = (uint32_t)__half_as_ushort(l0) | ((uint32_t)__half_as_ushort(l1)<<16);
        uint32_t lB = (uint32_t)__half_as_ushort(l2) | ((uint32_t)__half_as_ushort(l3)<<16);
        ((uint2*)g_xhi)[i] = make_uint2(hA,hB);
        ((uint2*)g_xlo)[i] = make_uint2(lA,lB);
    } else {
        int j = (b - NB_T1 - NB_T2 - NB_CX)*256 + tid;
        if (j < E_NUM) g_cnt[j] = 0;
        if (j < RCAP)  g_list[j] = -1;
    }
}

// ---------------- router ----------------
__global__ void router_kernel(const float* __restrict__ x, const float* __restrict__ rw){
    __shared__ float srw[E_NUM*H_DIM];
    __shared__ float red[128];
    int tid = threadIdx.x;
    for (int i = tid; i < E_NUM*H_DIM; i += 128) srw[i] = rw[i];
    __syncthreads();
    int t = blockIdx.x*128 + tid;
    const float* xr = x + (size_t)t*H_DIM;
    float l[E_NUM];
#pragma unroll
    for (int e = 0; e < E_NUM; e++) l[e] = 0.f;
    for (int h = 0; h < H_DIM; h++){
        float xv = xr[h];
#pragma unroll
        for (int e = 0; e < E_NUM; e++) l[e] += xv * srw[e*H_DIM + h];
    }
    int i0 = 0;
#pragma unroll
    for (int e = 1; e < E_NUM; e++) if (l[e] > l[i0]) i0 = e;
    int i1 = (i0 == 0) ? 1 : 0;
#pragma unroll
    for (int e = 0; e < E_NUM; e++) if (e != i0 && l[e] > l[i1]) i1 = e;
    float m2 = fmaxf(l[i0], l[i1]);
    float e0 = expf(l[i0]-m2), e1 = expf(l[i1]-m2);
    float inv = 1.f/(e0+e1);
    int p0 = atomicAdd(&g_cnt[i0],1);
    int p1 = atomicAdd(&g_cnt[i1],1);
    g_eidx[2*t]=i0; g_eidx[2*t+1]=i1;
    g_pos[2*t]=p0;  g_pos[2*t+1]=p1;
    g_wgt[2*t]=e0*inv; g_wgt[2*t+1]=e1*inv;

    float m8 = l[i0], p[E_NUM], s8 = 0.f;
#pragma unroll
    for (int e = 0; e < E_NUM; e++){ p[e] = expf(l[e]-m8); s8 += p[e]; }
    float is8 = 1.f/s8;
    for (int e = 0; e < E_NUM; e++){
        red[tid] = p[e]*is8;
        __syncthreads();
        for (int s = 64; s > 0; s >>= 1){ if (tid < s) red[tid] += red[tid+s]; __syncthreads(); }
        if (tid == 0) g_partsP[blockIdx.x][e] = red[0];
        __syncthreads();
    }
}

// ---------------- scatter (local prefix) ----------------
__global__ void scatter_kernel(){
    int i = blockIdx.x*blockDim.x + threadIdx.x;
    if (i < NROWS){
        int e = g_eidx[i];
        int base = 0;
#pragma unroll
        for (int q = 0; q < E_NUM; q++){
            int pad = ((g_cnt[q] + 127) >> 7) << 7;
            if (q < e) base += pad;
        }
        g_list[base + g_pos[i]] = i;
    }
}

// ---------------- GEMM1: fp16 2-term fused, 128 thr, BM=128 x f-width 64 ----------------
__global__ __launch_bounds__(128,2) void gemm1_mma(){
    int e = blockIdx.z;
    int m0 = blockIdx.y * BM;
    int f0 = blockIdx.x * 64;
    int tid = threadIdx.x;

    extern __shared__ char dsm[];
    __shared__ int stok[BM];
    __shared__ int sbc[2];

    if (tid == 0){
        int bacc = 0;
#pragma unroll
        for (int q = 0; q < E_NUM; q++){
            if (q < e) bacc += ((g_cnt[q] + 127) >> 7) << 7;
        }
        sbc[0] = bacc; sbc[1] = g_cnt[e];
    }
    __syncthreads();
    int base = sbc[0], cnt = sbc[1];
    if (m0 >= cnt) return;

    if (tid < BM){
        int li = g_list[base + m0 + tid];
        stok[tid] = (li < 0) ? -1 : (li >> 1);
    }
    __syncthreads();

    uint32_t sb = s2u(dsm);
    const char* xh = (const char*)g_xhi;
    const char* xl = (const char*)g_xlo;
    const char* bp = (const char*)g_b1h;

    // loader: 4 A descriptors (each feeds hi+lo) + 4 B descriptors
    uint32_t adst[4]; size_t aoff[4]; int anb[4];
    uint32_t bdst[4]; size_t boff[4];
#pragma unroll
    for (int j = 0; j < 4; j++){
        int flat = j*128 + tid;
        int r = (flat >> 2) & 127;
        int s = flat & 3;
        adst[j] = (uint32_t)(r*80 + s*16);
        int tok = stok[r];
        anb[j] = (tok < 0) ? 0 : 16;
        aoff[j] = (size_t)(tok < 0 ? 0 : tok)*2048 + s*16;
        bdst[j] = (uint32_t)(2*SUB1 + r*80 + s*16);
        int n = (r < 64) ? (f0 + r) : (F_DIM + f0 + (r - 64));
        boff[j] = ((size_t)e*N1 + n)*2048 + s*16;
    }

    // 4 warps: 2(m) x 2(n)
    int wid = tid >> 5, lane = tid & 31;
    int wm = wid & 1, wn = wid >> 1;
    int g = lane >> 2, tg = lane & 3;

    uint32_t aBase = (uint32_t)((wm*64 + (lane & 15))*80 + ((lane >> 4)*16));
    uint32_t bLane = (uint32_t)((((lane >> 4) << 3) + (lane & 7))*80 + (((lane >> 3) & 1)*16));
    uint32_t bPair[4];
    bPair[0] = 2*SUB1 + (uint32_t)(wn*32*80) + bLane;        // gate
    bPair[1] = bPair[0] + 16*80;
    bPair[2] = 2*SUB1 + (uint32_t)((64 + wn*32)*80) + bLane; // up
    bPair[3] = bPair[2] + 16*80;

    float accG[4][4][4], accU[4][4][4];
#pragma unroll
    for (int mt = 0; mt < 4; mt++)
#pragma unroll
        for (int nt = 0; nt < 4; nt++)
#pragma unroll
            for (int q = 0; q < 4; q++){ accG[mt][nt][q] = 0.f; accU[mt][nt][q] = 0.f; }

    // preload stages 0,1
#pragma unroll
    for (int s = 0; s < 2; s++){
        uint32_t stb = sb + s*STAGE;
        size_t ko = (size_t)s*64;
#pragma unroll
        for (int j = 0; j < 4; j++){
            cp16(stb + adst[j],        xh + aoff[j] + ko, anb[j]);
            cp16(stb + SUB1 + adst[j], xl + aoff[j] + ko, anb[j]);
            cp16(stb + bdst[j],        bp + boff[j] + ko, 16);
        }
        cp_commit();
    }

    for (int k = 0; k < NK1; k++){
        if (k + 1 < NK1) asm volatile("cp.async.wait_group 1;" ::: "memory");
        else             asm volatile("cp.async.wait_group 0;" ::: "memory");
        __syncthreads();
        if (k + 2 < NK1){
            uint32_t stb = sb + ((k+2) % NSTG)*STAGE;
            size_t ko = (size_t)(k+2)*64;
#pragma unroll
            for (int j = 0; j < 4; j++){
                cp16(stb + adst[j],        xh + aoff[j] + ko, anb[j]);
                cp16(stb + SUB1 + adst[j], xl + aoff[j] + ko, anb[j]);
                cp16(stb + bdst[j],        bp + boff[j] + ko, 16);
            }
            cp_commit();
        }

        uint32_t stb = sb + (k % NSTG)*STAGE;
#pragma unroll
        for (int ks = 0; ks < 2; ks++){
            uint32_t a[4][4], b[4][4];
#pragma unroll
            for (int mt = 0; mt < 4; mt++) ldmx4(a[mt], stb + aBase + mt*1280 + ks*32);
#pragma unroll
            for (int j = 0; j < 4; j++) ldmx4(b[j], stb + bPair[j] + ks*32);
            // T1: Ah * B
#pragma unroll
            for (int mt = 0; mt < 4; mt++)
#pragma unroll
                for (int t2 = 0; t2 < 2; t2++){
                    mma16816(accG[mt][0+t2], a[mt], b[0][2*t2], b[0][2*t2+1]);
                    mma16816(accG[mt][2+t2], a[mt], b[1][2*t2], b[1][2*t2+1]);
                    mma16816(accU[mt][0+t2], a[mt], b[2][2*t2], b[2][2*t2+1]);
                    mma16816(accU[mt][2+t2], a[mt], b[3][2*t2], b[3][2*t2+1]);
                }
            // T2: Al * B (reuse A regs)
#pragma unroll
            for (int mt = 0; mt < 4; mt++) ldmx4(a[mt], stb + SUB1 + aBase + mt*1280 + ks*32);
#pragma unroll
            for (int mt = 0; mt < 4; mt++)
#pragma unroll
                for (int t2 = 0; t2 < 2; t2++){
                    mma16816(accG[mt][0+t2], a[mt], b[0][2*t2], b[0][2*t2+1]);
                    mma16816(accG[mt][2+t2], a[mt], b[1][2*t2], b[1][2*t2+1]);
                    mma16816(accU[mt][0+t2], a[mt], b[2][2*t2], b[2][2*t2+1]);
                    mma16816(accU[mt][2+t2], a[mt], b[3][2*t2], b[3][2*t2+1]);
                }
        }
    }

    // fused SwiGLU epilogue -> fp16 hi/lo
#pragma unroll
    for (int mt = 0; mt < 4; mt++){
        size_t r0 = (size_t)(base + m0 + wm*64 + mt*16 + g);
        size_t r1 = r0 + 8;
#pragma unroll
        for (int nt = 0; nt < 4; nt++){
            int col = f0 + wn*32 + nt*8 + tg*2;
            float gv0 = accG[mt][nt][0], gv1 = accG[mt][nt][1];
            float uv0 = accU[mt][nt][0], uv1 = accU[mt][nt][1];
            float gv2 = accG[mt][nt][2], gv3 = accG[mt][nt][3];
            float uv2 = accU[mt][nt][2], uv3 = accU[mt][nt][3];
            float h0 = gv0/(1.f+__expf(-gv0))*uv0;
            float h1 = gv1/(1.f+__expf(-gv1))*uv1;
            float h2 = gv2/(1.f+__expf(-gv2))*uv2;
            float h3 = gv3/(1.f+__expf(-gv3))*uv3;
            __half bh, bl;
            uint32_t w, wl;
            split2h(h0, bh, bl); w  = (uint32_t)__half_as_ushort(bh);
            wl = (uint32_t)__half_as_ushort(bl);
            split2h(h1, bh, bl); w |= (uint32_t)__half_as_ushort(bh)<<16; wl |= (uint32_t)__half_as_ushort(bl)<<16;
            *(uint32_t*)&g_hh[r0*F_DIM + col] = w;
            *(uint32_t*)&g_hl[r0*F_DIM + col] = wl;
            split2h(h2, bh, bl); w  = (uint32_t)__half_as_ushort(bh); wl = (uint32_t)__half_as_ushort(bl);
            split2h(h3, bh, bl); w |= (uint32_t)__half_as_ushort(bh)<<16; wl |= (uint32_t)__half_as_ushort(bl)<<16;
            *(uint32_t*)&g_hh[r1*F_DIM + col] = w;
            *(uint32_t*)&g_hl[r1*F_DIM + col] = wl;
        }
    }
}

// ---------------- GEMM2: fp16 2-term fused, 128 thr, BM=128 x BN=128 ----------------
__global__ __launch_bounds__(128,2) void gemm2_mma(){
    int e = blockIdx.z;
    int m0 = blockIdx.y * BM;
    int n0 = blockIdx.x * 128;
    int tid = threadIdx.x;

    extern __shared__ char dsm[];
    __shared__ int   sli[BM];
    __shared__ float swt[BM];
    __shared__ int sbc[2];

    if (tid == 0){
        int bacc = 0;
#pragma unroll
        for (int q = 0; q < E_NUM; q++){
            if (q < e) bacc += ((g_cnt[q] + 127) >> 7) << 7;
        }
        sbc[0] = bacc; sbc[1] = g_cnt[e];
    }
    __syncthreads();
    int base = sbc[0], cnt = sbc[1];
    if (m0 >= cnt) return;

    if (tid < BM){
        int li = g_list[base + m0 + tid];
        sli[tid] = li;
        swt[tid] = (li < 0) ? 0.f : g_wgt[li];
    }
    __syncthreads();

    uint32_t sb = s2u(dsm);
    const char* ah = (const char*)g_hh;
    const char* al = (const char*)g_hl;
    const char* bp = (const char*)g_b2h;

    uint32_t adst[4]; size_t aoff[4];
    uint32_t bdst[4]; size_t boff[4];
#pragma unroll
    for (int j = 0; j < 4; j++){
        int flat = j*128 + tid;
        int r = (flat >> 2) & 127;
        int s = flat & 3;
        adst[j] = (uint32_t)(r*80 + s*16);
        aoff[j] = (size_t)(base + m0 + r)*5632 + s*16;
        bdst[j] = (uint32_t)(2*SUB1 + r*80 + s*16);
        boff[j] = ((size_t)e*H_DIM + n0 + r)*5632 + s*16;
    }

    int wid = tid >> 5, lane = tid & 31;
    int wm = wid & 1, wn = wid >> 1;
    int g = lane >> 2, tg = lane & 3;

    uint32_t aBase = (uint32_t)((wm*64 + (lane & 15))*80 + ((lane >> 4)*16));
    uint32_t bLane = (uint32_t)((((lane >> 4) << 3) + (lane & 7))*80 + (((lane >> 3) & 1)*16));
    uint32_t bPair[4];
#pragma unroll
    for (int j = 0; j < 4; j++) bPair[j] = 2*SUB1 + (uint32_t)((wn*64 + j*16)*80) + bLane;

    float acc[4][8][4];
#pragma unroll
    for (int mt = 0; mt < 4; mt++)
#pragma unroll
        for (int nt = 0; nt < 8; nt++)
#pragma unroll
            for (int q = 0; q < 4; q++) acc[mt][nt][q] = 0.f;

#pragma unroll
    for (int s = 0; s < 2; s++){
        uint32_t stb = sb + s*STAGE;
        size_t ko = (size_t)s*64;
#pragma unroll
        for (int j = 0; j < 4; j++){
            cp16(stb + adst[j],        ah + aoff[j] + ko, 16);
            cp16(stb + SUB1 + adst[j], al + aoff[j] + ko, 16);
            cp16(stb + bdst[j],        bp + boff[j] + ko, 16);
        }
        cp_commit();
    }

    for (int k = 0; k < NK2; k++){
        if (k + 1 < NK2) asm volatile("cp.async.wait_group 1;" ::: "memory");
        else             asm volatile("cp.async.wait_group 0;" ::: "memory");
        __syncthreads();
        if (k + 2 < NK2){
            uint32_t stb = sb + ((k+2) % NSTG)*STAGE;
            size_t ko = (size_t)(k+2)*64;
#pragma unroll
            for (int j = 0; j < 4; j++){
                cp16(stb + adst[j],        ah + aoff[j] + ko, 16);
                cp16(stb + SUB1 + adst[j], al + aoff[j] + ko, 16);
                cp16(stb + bdst[j],        bp + boff[j] + ko, 16);
            }
            cp_commit();
        }

        uint32_t stb = sb + (k % NSTG)*STAGE;
#pragma unroll
        for (int ks = 0; ks < 2; ks++){
            uint32_t a[4][4], b[4][4];
#pragma unroll
            for (int mt = 0; mt < 4; mt++) ldmx4(a[mt], stb + aBase + mt*1280 + ks*32);
#pragma unroll
            for (int j = 0; j < 4; j++) ldmx4(b[j], stb + bPair[j] + ks*32);
            // T1: Ah * B
#pragma unroll
            for (int mt = 0; mt < 4; mt++)
#pragma unroll
                for (int j = 0; j < 4; j++){
                    mma16816(acc[mt][2*j],   a[mt], b[j][0], b[j][1]);
                    mma16816(acc[mt][2*j+1], a[mt], b[j][2], b[j][3]);
                }
            // T2: Al * B
#pragma unroll
            for (int mt = 0; mt < 4; mt++) ldmx4(a[mt], stb + SUB1 + aBase + mt*1280 + ks*32);
#pragma unroll
            for (int mt = 0; mt < 4; mt++)
#pragma unroll
                for (int j = 0; j < 4; j++){
                    mma16816(acc[mt][2*j],   a[mt], b[j][0], b[j][1]);
                    mma16816(acc[mt][2*j+1], a[mt], b[j][2], b[j][3]);
                }
        }
    }

    // scaled epilogue -> g_y
#pragma unroll
    for (int mt = 0; mt < 4; mt++){
        int rl0 = wm*64 + mt*16 + g;
        int rl1 = rl0 + 8;
        int li0 = sli[rl0], li1 = sli[rl1];
        float w0 = swt[rl0], w1 = swt[rl1];
#pragma unroll
        for (int nt = 0; nt < 8; nt++){
            int col = n0 + wn*64 + nt*8 + tg*2;
            if (li0 >= 0){
                float2 v = make_float2(acc[mt][nt][0]*w0, acc[mt][nt][1]*w0);
                *(float2*)&g_y[(size_t)li0*H_DIM + col] = v;
            }
            if (li1 >= 0){
                float2 v = make_float2(acc[mt][nt][2]*w1, acc[mt][nt][3]*w1);
                *(float2*)&g_y[(size_t)li1*H_DIM + col] = v;
            }
        }
    }
}

// ---------------- combine + aux ----------------
__global__ void combine_kernel(float* __restrict__ out){
    long long gid = (long long)blockIdx.x*256 + threadIdx.x;
    if (gid >= (long long)T_TOK*H_DIM/4) return;
    int t = (int)(gid >> 8);
    int c = (int)(gid & 255) * 4;
    float4 a = *(const float4*)&g_y[(size_t)(2*t)*H_DIM + c];
    float4 b = *(const float4*)&g_y[(size_t)(2*t+1)*H_DIM + c];
    *(float4*)&out[(size_t)t*H_DIM + c] = make_float4(a.x+b.x, a.y+b.y, a.z+b.z, a.w+b.w);
}
__global__ void aux_kernel(float* __restrict__ out){
    if (threadIdx.x == 0){
        float aux = 0.f;
        for (int e = 0; e < E_NUM; e++){
            float P = 0.f;
            for (int b = 0; b < NBLK_ROUTER; b++) P += g_partsP[b][e];
            P *= (1.f/(float)T_TOK);
            float f = (float)g_cnt[e] / (float)NROWS;
            aux += f*P;
        }
        out[(size_t)T_TOK*H_DIM] = (float)E_NUM * aux;
    }
}

// ---------------- launch ----------------
extern "C" void kernel_launch(void* const* d_in, const int* in_sizes, int n_in,
                              void* d_out, int out_size){
    const float* x  = (const float*)d_in[0];
    const float* rw = (const float*)d_in[1];
    const float* wg = (const float*)d_in[2];
    const float* wu = (const float*)d_in[3];
    const float* wd = (const float*)d_in[4];
    float* out = (float*)d_out;

    cudaFuncSetAttribute(gemm1_mma, cudaFuncAttributeMaxDynamicSharedMemorySize, SMEM_DYN);
    cudaFuncSetAttribute(gemm2_mma, cudaFuncAttributeMaxDynamicSharedMemorySize, SMEM_DYN);

    prep_kernel<<<NB_T1 + NB_T2 + NB_CX + NB_IN, 256>>>(x, wg, wu, wd);
    router_kernel<<<NBLK_ROUTER, 128>>>(x, rw);
    scatter_kernel<<<(NROWS+255)/256, 256>>>();

    gemm1_mma<<<dim3(F_DIM/64, T_TOK/BM, E_NUM), 128, SMEM_DYN>>>();
    gemm2_mma<<<dim3(H_DIM/128, T_TOK/BM, E_NUM), 128, SMEM_DYN>>>();

    combine_kernel<<<(int)(((long long)T_TOK*H_DIM/4 + 255)/256), 256>>>(out);
    if (out_size > T_TOK*H_DIM) aux_kernel<<<1, 32>>>(out);
}

// round 14
// speedup vs baseline: 1.6716x; 1.6716x over previous
#include <cuda_runtime.h>
#include <cuda_fp16.h>
#include <math.h>
#include <stdint.h>

// ---------------- problem constants ----------------
#define T_TOK 4096
#define H_DIM 1024
#define F_DIM 2816
#define E_NUM 8
#define NROWS (T_TOK*2)
#define BM 128
#define RCAP (NROWS + E_NUM*BM)   // 9216
#define N1 (2*F_DIM)              // 5632
#define NBLK_ROUTER 32
#define STAGE 20480               // (128 A rows + 128 B rows) x 80B
#define NSTG 5
#define SMEM_DYN (NSTG*STAGE)     // 102400
#define NK1 32                    // 1024/32 (single pass)
#define NK2 88                    // 2816/32 (single pass)
// prep kernel block partition
#define NB_T1 22528
#define NB_T2 22528
#define NB_CX 4096
#define NB_IN 36

// ---------------- device scratch ----------------
__device__ int   g_eidx[NROWS];
__device__ float g_wgt[NROWS];
__device__ int   g_cnt[E_NUM];
__device__ int   g_pos[NROWS];
__device__ int   g_list[RCAP];
__device__ float g_partsP[NBLK_ROUTER][E_NUM];

__device__ __align__(16) __half g_xh[(size_t)T_TOK*H_DIM];
__device__ __align__(16) __half g_b1h[(size_t)E_NUM*N1*H_DIM];   // [e][n(gate|up)][h]
__device__ __align__(16) __half g_b2h[(size_t)E_NUM*H_DIM*F_DIM];// [e][n(h)][f]
__device__ __align__(16) __half g_hh[(size_t)RCAP*F_DIM];
__device__ __align__(16) float g_y[(size_t)NROWS*H_DIM];

// ---------------- PTX helpers ----------------
__device__ __forceinline__ uint32_t s2u(const void* p){
    uint32_t a;
    asm("{ .reg .u64 t; cvta.to.shared.u64 t, %1; cvt.u32.u64 %0, t; }" : "=r"(a) : "l"(p));
    return a;
}
__device__ __forceinline__ void cp16(uint32_t dst, const void* src, int n){
    asm volatile("cp.async.cg.shared.global [%0], [%1], 16, %2;" :: "r"(dst), "l"(src), "r"(n) : "memory");
}
__device__ __forceinline__ void cp_commit(){ asm volatile("cp.async.commit_group;" ::: "memory"); }
__device__ __forceinline__ void ldmx4(uint32_t* r, uint32_t addr){
    asm volatile("ldmatrix.sync.aligned.m8n8.x4.shared.b16 {%0,%1,%2,%3}, [%4];"
        : "=r"(r[0]),"=r"(r[1]),"=r"(r[2]),"=r"(r[3]) : "r"(addr));
}
__device__ __forceinline__ void mma16816(float* c, const uint32_t* a, uint32_t b0, uint32_t b1){
    asm volatile("mma.sync.aligned.m16n8k16.row.col.f32.f16.f16.f32 "
                 "{%0,%1,%2,%3},{%4,%5,%6,%7},{%8,%9},{%0,%1,%2,%3};"
        : "+f"(c[0]),"+f"(c[1]),"+f"(c[2]),"+f"(c[3])
        : "r"(a[0]),"r"(a[1]),"r"(a[2]),"r"(a[3]), "r"(b0),"r"(b1));
}

// ---------------- prep: t1 + t2 + convx + init fused ----------------
__global__ void prep_kernel(const float* __restrict__ x,
                            const float* __restrict__ wg,
                            const float* __restrict__ wu,
                            const float* __restrict__ wd){
    __shared__ float sg[32][33], su[32][33];
    int b = blockIdx.x;
    int tid = threadIdx.x;
    int tx = tid & 31, ty = tid >> 5;

    if (b < NB_T1){
        int e = b / 2816, rem = b % 2816;
        int h0 = (rem / 88) * 32, f0 = (rem % 88) * 32;
        const float* pg = wg + ((size_t)e*H_DIM + h0)*F_DIM + f0;
        const float* pu = wu + ((size_t)e*H_DIM + h0)*F_DIM + f0;
#pragma unroll
        for (int j = 0; j < 4; j++){
            int hl = ty + j*8;
            sg[hl][tx] = pg[(size_t)hl*F_DIM + tx];
            su[hl][tx] = pu[(size_t)hl*F_DIM + tx];
        }
        __syncthreads();
#pragma unroll
        for (int j = 0; j < 4; j++){
            int fl = ty + j*8;
            size_t ng = ((size_t)e*N1 + f0 + fl)*H_DIM + h0 + tx;
            size_t nu = ((size_t)e*N1 + F_DIM + f0 + fl)*H_DIM + h0 + tx;
            g_b1h[ng] = __float2half_rn(sg[tx][fl]);
            g_b1h[nu] = __float2half_rn(su[tx][fl]);
        }
    } else if (b < NB_T1 + NB_T2){
        int bb = b - NB_T1;
        int e = bb / 2816, rem = bb % 2816;
        int h0 = (rem / 88) * 32, f0 = (rem % 88) * 32;
        const float* pd = wd + ((size_t)e*F_DIM + f0)*H_DIM + h0;
#pragma unroll
        for (int j = 0; j < 4; j++){
            int fl = ty + j*8;
            sg[fl][tx] = pd[(size_t)fl*H_DIM + tx];
        }
        __syncthreads();
#pragma unroll
        for (int j = 0; j < 4; j++){
            int hl = ty + j*8;
            size_t o = ((size_t)e*H_DIM + h0 + hl)*F_DIM + f0 + tx;
            g_b2h[o] = __float2half_rn(sg[tx][hl]);
        }
    } else if (b < NB_T1 + NB_T2 + NB_CX){
        int i = (b - NB_T1 - NB_T2)*256 + tid;
        float4 v = ((const float4*)x)[i];
        uint32_t hA = (uint32_t)__half_as_ushort(__float2half_rn(v.x)) |
                      ((uint32_t)__half_as_ushort(__float2half_rn(v.y))<<16);
        uint32_t hB = (uint32_t)__half_as_ushort(__float2half_rn(v.z)) |
                      ((uint32_t)__half_as_ushort(__float2half_rn(v.w))<<16);
        ((uint2*)g_xh)[i] = make_uint2(hA,hB);
    } else {
        int j = (b - NB_T1 - NB_T2 - NB_CX)*256 + tid;
        if (j < E_NUM) g_cnt[j] = 0;
        if (j < RCAP)  g_list[j] = -1;
    }
}

// ---------------- router ----------------
__global__ void router_kernel(const float* __restrict__ x, const float* __restrict__ rw){
    __shared__ float srw[E_NUM*H_DIM];
    __shared__ float red[128];
    int tid = threadIdx.x;
    for (int i = tid; i < E_NUM*H_DIM; i += 128) srw[i] = rw[i];
    __syncthreads();
    int t = blockIdx.x*128 + tid;
    const float* xr = x + (size_t)t*H_DIM;
    float l[E_NUM];
#pragma unroll
    for (int e = 0; e < E_NUM; e++) l[e] = 0.f;
    for (int h = 0; h < H_DIM; h++){
        float xv = xr[h];
#pragma unroll
        for (int e = 0; e < E_NUM; e++) l[e] += xv * srw[e*H_DIM + h];
    }
    int i0 = 0;
#pragma unroll
    for (int e = 1; e < E_NUM; e++) if (l[e] > l[i0]) i0 = e;
    int i1 = (i0 == 0) ? 1 : 0;
#pragma unroll
    for (int e = 0; e < E_NUM; e++) if (e != i0 && l[e] > l[i1]) i1 = e;
    float m2 = fmaxf(l[i0], l[i1]);
    float e0 = expf(l[i0]-m2), e1 = expf(l[i1]-m2);
    float inv = 1.f/(e0+e1);
    int p0 = atomicAdd(&g_cnt[i0],1);
    int p1 = atomicAdd(&g_cnt[i1],1);
    g_eidx[2*t]=i0; g_eidx[2*t+1]=i1;
    g_pos[2*t]=p0;  g_pos[2*t+1]=p1;
    g_wgt[2*t]=e0*inv; g_wgt[2*t+1]=e1*inv;

    float m8 = l[i0], p[E_NUM], s8 = 0.f;
#pragma unroll
    for (int e = 0; e < E_NUM; e++){ p[e] = expf(l[e]-m8); s8 += p[e]; }
    float is8 = 1.f/s8;
    for (int e = 0; e < E_NUM; e++){
        red[tid] = p[e]*is8;
        __syncthreads();
        for (int s = 64; s > 0; s >>= 1){ if (tid < s) red[tid] += red[tid+s]; __syncthreads(); }
        if (tid == 0) g_partsP[blockIdx.x][e] = red[0];
        __syncthreads();
    }
}

// ---------------- scatter (local prefix) ----------------
__global__ void scatter_kernel(){
    int i = blockIdx.x*blockDim.x + threadIdx.x;
    if (i < NROWS){
        int e = g_eidx[i];
        int base = 0;
#pragma unroll
        for (int q = 0; q < E_NUM; q++){
            int pad = ((g_cnt[q] + 127) >> 7) << 7;
            if (q < e) base += pad;
        }
        g_list[base + g_pos[i]] = i;
    }
}

// ---------------- GEMM1: fp16 single-pass, 128 thr, BM=128 x f-width 64 ----------------
__global__ __launch_bounds__(128,2) void gemm1_mma(){
    int e = blockIdx.z;
    int m0 = blockIdx.y * BM;
    int f0 = blockIdx.x * 64;
    int tid = threadIdx.x;

    extern __shared__ char dsm[];
    __shared__ int stok[BM];
    __shared__ int sbc[2];

    if (tid == 0){
        int bacc = 0;
#pragma unroll
        for (int q = 0; q < E_NUM; q++){
            if (q < e) bacc += ((g_cnt[q] + 127) >> 7) << 7;
        }
        sbc[0] = bacc; sbc[1] = g_cnt[e];
    }
    __syncthreads();
    int base = sbc[0], cnt = sbc[1];
    if (m0 >= cnt) return;

    if (tid < BM){
        int li = g_list[base + m0 + tid];
        stok[tid] = (li < 0) ? -1 : (li >> 1);
    }
    __syncthreads();

    uint32_t sb = s2u(dsm);
    const char* pA = (const char*)g_xh;
    const char* pB = (const char*)g_b1h;

    // 8 loader slots per thread: 1024 x 16B per stage (A 512, B 512)
    uint32_t dsto[8]; size_t soff[8]; int isA[8], nb[8];
#pragma unroll
    for (int i = 0; i < 8; i++){
        int flat = i*128 + tid;
        int tile = flat >> 9;              // 0 = A, 1 = B
        int r    = (flat >> 2) & 127;
        int slot = flat & 3;
        dsto[i] = (uint32_t)(tile*10240 + r*80 + slot*16);
        if (tile == 0){
            int tok = stok[r];
            isA[i] = 1;
            if (tok < 0){ nb[i] = 0; soff[i] = 0; }
            else { nb[i] = 16; soff[i] = (size_t)tok*2048 + slot*16; }
        } else {
            int n = (r < 64) ? (f0 + r) : (F_DIM + f0 + (r - 64));
            isA[i] = 0; nb[i] = 16;
            soff[i] = ((size_t)e*N1 + n)*2048 + slot*16;
        }
    }

    // 4 warps: 2(m) x 2(n)
    int wid = tid >> 5, lane = tid & 31;
    int wm = wid & 1, wn = wid >> 1;
    int g = lane >> 2, tg = lane & 3;

    uint32_t aBase = (uint32_t)((wm*64 + (lane & 15))*80 + ((lane >> 4)*16));
    uint32_t bLane = (uint32_t)((((lane >> 4) << 3) + (lane & 7))*80 + (((lane >> 3) & 1)*16));
    uint32_t bPair[4];
    bPair[0] = 10240 + (uint32_t)(wn*32*80) + bLane;        // gate
    bPair[1] = bPair[0] + 16*80;
    bPair[2] = 10240 + (uint32_t)((64 + wn*32)*80) + bLane; // up
    bPair[3] = bPair[2] + 16*80;

    float accG[4][4][4], accU[4][4][4];
#pragma unroll
    for (int mt = 0; mt < 4; mt++)
#pragma unroll
        for (int nt = 0; nt < 4; nt++)
#pragma unroll
            for (int q = 0; q < 4; q++){ accG[mt][nt][q] = 0.f; accU[mt][nt][q] = 0.f; }

    // preload stages 0..2
#pragma unroll
    for (int s = 0; s < 3; s++){
        uint32_t stb = sb + s*STAGE;
#pragma unroll
        for (int i = 0; i < 8; i++)
            cp16(stb + dsto[i], (isA[i] ? pA : pB) + soff[i] + (size_t)s*64, nb[i]);
        cp_commit();
    }

    for (int k = 0; k < NK1; k++){
        if (k + 3 < NK1){
            int kk = k + 3;
            uint32_t stb = sb + (kk % NSTG)*STAGE;
#pragma unroll
            for (int i = 0; i < 8; i++)
                cp16(stb + dsto[i], (isA[i] ? pA : pB) + soff[i] + (size_t)kk*64, nb[i]);
            cp_commit();
            asm volatile("cp.async.wait_group 3;" ::: "memory");
        } else if (k + 2 < NK1){
            asm volatile("cp.async.wait_group 2;" ::: "memory");
        } else if (k + 1 < NK1){
            asm volatile("cp.async.wait_group 1;" ::: "memory");
        } else {
            asm volatile("cp.async.wait_group 0;" ::: "memory");
        }
        __syncthreads();

        uint32_t stb = sb + (k % NSTG)*STAGE;
#pragma unroll
        for (int ks = 0; ks < 2; ks++){
            uint32_t a[4][4];
#pragma unroll
            for (int mt = 0; mt < 4; mt++) ldmx4(a[mt], stb + aBase + mt*1280 + ks*32);
            uint32_t b[4][4];
#pragma unroll
            for (int j = 0; j < 4; j++) ldmx4(b[j], stb + bPair[j] + ks*32);
#pragma unroll
            for (int mt = 0; mt < 4; mt++){
#pragma unroll
                for (int t2 = 0; t2 < 2; t2++){
                    mma16816(accG[mt][0+t2], a[mt], b[0][2*t2], b[0][2*t2+1]);
                    mma16816(accG[mt][2+t2], a[mt], b[1][2*t2], b[1][2*t2+1]);
                    mma16816(accU[mt][0+t2], a[mt], b[2][2*t2], b[2][2*t2+1]);
                    mma16816(accU[mt][2+t2], a[mt], b[3][2*t2], b[3][2*t2+1]);
                }
            }
        }
    }

    // fused SwiGLU epilogue -> fp16 h
#pragma unroll
    for (int mt = 0; mt < 4; mt++){
        size_t r0 = (size_t)(base + m0 + wm*64 + mt*16 + g);
        size_t r1 = r0 + 8;
#pragma unroll
        for (int nt = 0; nt < 4; nt++){
            int col = f0 + wn*32 + nt*8 + tg*2;
            float gv0 = accG[mt][nt][0], gv1 = accG[mt][nt][1];
            float uv0 = accU[mt][nt][0], uv1 = accU[mt][nt][1];
            float gv2 = accG[mt][nt][2], gv3 = accG[mt][nt][3];
            float uv2 = accU[mt][nt][2], uv3 = accU[mt][nt][3];
            float h0 = gv0/(1.f+__expf(-gv0))*uv0;
            float h1 = gv1/(1.f+__expf(-gv1))*uv1;
            float h2 = gv2/(1.f+__expf(-gv2))*uv2;
            float h3 = gv3/(1.f+__expf(-gv3))*uv3;
            uint32_t w;
            w  = (uint32_t)__half_as_ushort(__float2half_rn(h0));
            w |= (uint32_t)__half_as_ushort(__float2half_rn(h1))<<16;
            *(uint32_t*)&g_hh[r0*F_DIM + col] = w;
            w  = (uint32_t)__half_as_ushort(__float2half_rn(h2));
            w |= (uint32_t)__half_as_ushort(__float2half_rn(h3))<<16;
            *(uint32_t*)&g_hh[r1*F_DIM + col] = w;
        }
    }
}

// ---------------- GEMM2: fp16 single-pass, 128 thr, BM=128 x BN=128 ----------------
__global__ __launch_bounds__(128,2) void gemm2_mma(){
    int e = blockIdx.z;
    int m0 = blockIdx.y * BM;
    int n0 = blockIdx.x * 128;
    int tid = threadIdx.x;

    extern __shared__ char dsm[];
    __shared__ int   sli[BM];
    __shared__ float swt[BM];
    __shared__ int sbc[2];

    if (tid == 0){
        int bacc = 0;
#pragma unroll
        for (int q = 0; q < E_NUM; q++){
            if (q < e) bacc += ((g_cnt[q] + 127) >> 7) << 7;
        }
        sbc[0] = bacc; sbc[1] = g_cnt[e];
    }
    __syncthreads();
    int base = sbc[0], cnt = sbc[1];
    if (m0 >= cnt) return;

    if (tid < BM){
        int li = g_list[base + m0 + tid];
        sli[tid] = li;
        swt[tid] = (li < 0) ? 0.f : g_wgt[li];
    }
    __syncthreads();

    uint32_t sb = s2u(dsm);
    const char* pA = (const char*)g_hh;
    const char* pB = (const char*)g_b2h;

    uint32_t dsto[8]; size_t soff[8]; int isA[8];
#pragma unroll
    for (int i = 0; i < 8; i++){
        int flat = i*128 + tid;
        int tile = flat >> 9;
        int r    = (flat >> 2) & 127;
        int slot = flat & 3;
        dsto[i] = (uint32_t)(tile*10240 + r*80 + slot*16);
        if (tile == 0){
            isA[i] = 1;
            soff[i] = (size_t)(base + m0 + r)*5632 + slot*16;
        } else {
            isA[i] = 0;
            soff[i] = ((size_t)e*H_DIM + n0 + r)*5632 + slot*16;
        }
    }

    int wid = tid >> 5, lane = tid & 31;
    int wm = wid & 1, wn = wid >> 1;
    int g = lane >> 2, tg = lane & 3;

    uint32_t aBase = (uint32_t)((wm*64 + (lane & 15))*80 + ((lane >> 4)*16));
    uint32_t bLane = (uint32_t)((((lane >> 4) << 3) + (lane & 7))*80 + (((lane >> 3) & 1)*16));
    uint32_t bPair[4];
#pragma unroll
    for (int j = 0; j < 4; j++) bPair[j] = 10240 + (uint32_t)((wn*64 + j*16)*80) + bLane;

    float acc[4][8][4];
#pragma unroll
    for (int mt = 0; mt < 4; mt++)
#pragma unroll
        for (int nt = 0; nt < 8; nt++)
#pragma unroll
            for (int q = 0; q < 4; q++) acc[mt][nt][q] = 0.f;

#pragma unroll
    for (int s = 0; s < 3; s++){
        uint32_t stb = sb + s*STAGE;
#pragma unroll
        for (int i = 0; i < 8; i++)
            cp16(stb + dsto[i], (isA[i] ? pA : pB) + soff[i] + (size_t)s*64, 16);
        cp_commit();
    }

    for (int k = 0; k < NK2; k++){
        if (k + 3 < NK2){
            int kk = k + 3;
            uint32_t stb = sb + (kk % NSTG)*STAGE;
#pragma unroll
            for (int i = 0; i < 8; i++)
                cp16(stb + dsto[i], (isA[i] ? pA : pB) + soff[i] + (size_t)kk*64, 16);
            cp_commit();
            asm volatile("cp.async.wait_group 3;" ::: "memory");
        } else if (k + 2 < NK2){
            asm volatile("cp.async.wait_group 2;" ::: "memory");
        } else if (k + 1 < NK2){
            asm volatile("cp.async.wait_group 1;" ::: "memory");
        } else {
            asm volatile("cp.async.wait_group 0;" ::: "memory");
        }
        __syncthreads();

        uint32_t stb = sb + (k % NSTG)*STAGE;
#pragma unroll
        for (int ks = 0; ks < 2; ks++){
            uint32_t a[4][4];
#pragma unroll
            for (int mt = 0; mt < 4; mt++) ldmx4(a[mt], stb + aBase + mt*1280 + ks*32);
            uint32_t b[4][4];
#pragma unroll
            for (int j = 0; j < 4; j++) ldmx4(b[j], stb + bPair[j] + ks*32);
#pragma unroll
            for (int mt = 0; mt < 4; mt++){
#pragma unroll
                for (int j = 0; j < 4; j++){
                    mma16816(acc[mt][2*j],   a[mt], b[j][0], b[j][1]);
                    mma16816(acc[mt][2*j+1], a[mt], b[j][2], b[j][3]);
                }
            }
        }
    }

    // scaled epilogue -> g_y
#pragma unroll
    for (int mt = 0; mt < 4; mt++){
        int rl0 = wm*64 + mt*16 + g;
        int rl1 = rl0 + 8;
        int li0 = sli[rl0], li1 = sli[rl1];
        float w0 = swt[rl0], w1 = swt[rl1];
#pragma unroll
        for (int nt = 0; nt < 8; nt++){
            int col = n0 + wn*64 + nt*8 + tg*2;
            if (li0 >= 0){
                float2 v = make_float2(acc[mt][nt][0]*w0, acc[mt][nt][1]*w0);
                *(float2*)&g_y[(size_t)li0*H_DIM + col] = v;
            }
            if (li1 >= 0){
                float2 v = make_float2(acc[mt][nt][2]*w1, acc[mt][nt][3]*w1);
                *(float2*)&g_y[(size_t)li1*H_DIM + col] = v;
            }
        }
    }
}

// ---------------- combine + aux ----------------
__global__ void combine_kernel(float* __restrict__ out){
    long long gid = (long long)blockIdx.x*256 + threadIdx.x;
    if (gid >= (long long)T_TOK*H_DIM/4) return;
    int t = (int)(gid >> 8);
    int c = (int)(gid & 255) * 4;
    float4 a = *(const float4*)&g_y[(size_t)(2*t)*H_DIM + c];
    float4 b = *(const float4*)&g_y[(size_t)(2*t+1)*H_DIM + c];
    *(float4*)&out[(size_t)t*H_DIM + c] = make_float4(a.x+b.x, a.y+b.y, a.z+b.z, a.w+b.w);
}
__global__ void aux_kernel(float* __restrict__ out){
    if (threadIdx.x == 0){
        float aux = 0.f;
        for (int e = 0; e < E_NUM; e++){
            float P = 0.f;
            for (int b = 0; b < NBLK_ROUTER; b++) P += g_partsP[b][e];
            P *= (1.f/(float)T_TOK);
            float f = (float)g_cnt[e] / (float)NROWS;
            aux += f*P;
        }
        out[(size_t)T_TOK*H_DIM] = (float)E_NUM * aux;
    }
}

// ---------------- launch ----------------
extern "C" void kernel_launch(void* const* d_in, const int* in_sizes, int n_in,
                              void* d_out, int out_size){
    const float* x  = (const float*)d_in[0];
    const float* rw = (const float*)d_in[1];
    const float* wg = (const float*)d_in[2];
    const float* wu = (const float*)d_in[3];
    const float* wd = (const float*)d_in[4];
    float* out = (float*)d_out;

    cudaFuncSetAttribute(gemm1_mma, cudaFuncAttributeMaxDynamicSharedMemorySize, SMEM_DYN);
    cudaFuncSetAttribute(gemm2_mma, cudaFuncAttributeMaxDynamicSharedMemorySize, SMEM_DYN);

    prep_kernel<<<NB_T1 + NB_T2 + NB_CX + NB_IN, 256>>>(x, wg, wu, wd);
    router_kernel<<<NBLK_ROUTER, 128>>>(x, rw);
    scatter_kernel<<<(NROWS+255)/256, 256>>>();

    gemm1_mma<<<dim3(F_DIM/64, T_TOK/BM, E_NUM), 128, SMEM_DYN>>>();
    gemm2_mma<<<dim3(H_DIM/128, T_TOK/BM, E_NUM), 128, SMEM_DYN>>>();

    combine_kernel<<<(int)(((long long)T_TOK*H_DIM/4 + 255)/256), 256>>>(out);
    if (out_size > T_TOK*H_DIM) aux_kernel<<<1, 32>>>(out);
}